// round 1
// baseline (speedup 1.0000x reference)
#include <cuda_runtime.h>

#define N_NODES 100000
#define F_DIM   256
#define E_DIM   128
#define B_DIM   8192
#define D_DIM   32
#define K_SEL   16
#define CAT_DIM 640   // F + 3E

// Scratch (static device globals — no allocations allowed)
__device__ float g_scores[N_NODES * 2];          // [N][2]
__device__ float g_mean[3 * B_DIM * F_DIM];      // [3][B][F] mean features
__device__ float g_cat[B_DIM * CAT_DIM];         // [B][640] = [self | r1 | r2 | r3]

// ---------------------------------------------------------------------------
// K1: scores[n] = features[n] @ wc + bc, for all N. One warp per node.
// ---------------------------------------------------------------------------
__global__ void k_scores(const float* __restrict__ feat,
                         const float* __restrict__ wc,
                         const float* __restrict__ bc) {
    int gwarp = (blockIdx.x * blockDim.x + threadIdx.x) >> 5;
    int lane  = threadIdx.x & 31;
    if (gwarp >= N_NODES) return;
    const float* row = feat + (size_t)gwarp * F_DIM;
    float s0 = 0.f, s1 = 0.f;
#pragma unroll
    for (int k = 0; k < 8; k++) {
        int f = k * 32 + lane;
        float v = row[f];
        s0 += v * __ldg(&wc[f * 2 + 0]);
        s1 += v * __ldg(&wc[f * 2 + 1]);
    }
#pragma unroll
    for (int o = 16; o; o >>= 1) {
        s0 += __shfl_down_sync(0xFFFFFFFFu, s0, o);
        s1 += __shfl_down_sync(0xFFFFFFFFu, s1, o);
    }
    if (lane == 0) {
        g_scores[gwarp * 2 + 0] = s0 + bc[0];
        g_scores[gwarp * 2 + 1] = s1 + bc[1];
    }
}

// ---------------------------------------------------------------------------
// K2a: center_scores = scores[nodes] -> d_out tail
// ---------------------------------------------------------------------------
__global__ void k_center(const int* __restrict__ nodes, float* __restrict__ out) {
    int b = blockIdx.x * blockDim.x + threadIdx.x;
    if (b < B_DIM) {
        int n = nodes[b];
        out[b * 2 + 0] = g_scores[n * 2 + 0];
        out[b * 2 + 1] = g_scores[n * 2 + 1];
    }
}

// ---------------------------------------------------------------------------
// K2b: self-feature gather into g_cat[:, 0:256]
// ---------------------------------------------------------------------------
__global__ void k_self(const float* __restrict__ feat, const int* __restrict__ nodes) {
    int b = blockIdx.x;
    int t = threadIdx.x;  // 256
    g_cat[(size_t)b * CAT_DIM + t] = feat[(size_t)nodes[b] * F_DIM + t];
}

// ---------------------------------------------------------------------------
// K3: per (b, relation): stable top-K=16 by |s1[neigh]-c|, then mean of the
// 16 selected feature rows -> g_mean. 256 threads: warp0 selects, all sum.
// ---------------------------------------------------------------------------
__global__ void k_relsum(const float* __restrict__ feat,
                         const int* __restrict__ nodes,
                         const int* __restrict__ n1,
                         const int* __restrict__ n2,
                         const int* __restrict__ n3) {
    int b = blockIdx.x;
    int r = blockIdx.y;
    int t = threadIdx.x;

    __shared__ float s_dist[D_DIM];
    __shared__ int   s_idx[D_DIM];
    __shared__ int   s_sel[K_SEL];

    const int* nb = (r == 0 ? n1 : (r == 1 ? n2 : n3)) + (size_t)b * D_DIM;

    if (t < D_DIM) {
        int idx = nb[t];
        s_idx[t] = idx;
        float c = g_scores[nodes[b] * 2 + 1];
        s_dist[t] = fabsf(g_scores[idx * 2 + 1] - c);
    }
    __syncthreads();
    if (t < D_DIM) {
        float d = s_dist[t];
        int rank = 0;
#pragma unroll
        for (int j = 0; j < D_DIM; j++) {
            float dj = s_dist[j];
            rank += (dj < d) || (dj == d && j < t);  // stable: matches jax top_k
        }
        if (rank < K_SEL) s_sel[rank] = s_idx[t];
    }
    __syncthreads();

    // gather-sum 16 rows, column t
    int sel[K_SEL];
#pragma unroll
    for (int k = 0; k < K_SEL; k++) sel[k] = s_sel[k];
    float acc = 0.f;
#pragma unroll
    for (int k = 0; k < K_SEL; k++)
        acc += __ldg(&feat[(size_t)sel[k] * F_DIM + t]);

    g_mean[((size_t)r * B_DIM + b) * F_DIM + t] = acc * (1.0f / K_SEL);
}

// ---------------------------------------------------------------------------
// GEMM tiles: BM=64, BN=128, BK=16, 256 threads, per-thread 4x8 accumulators
// ---------------------------------------------------------------------------
#define BM 64
#define BN 128
#define BK 16

// K4: r_i = relu(g_mean[r] @ w_r) -> g_cat[:, 256 + r*128 : ...]
__global__ void k_relgemm(const float* __restrict__ w1,
                          const float* __restrict__ w2,
                          const float* __restrict__ w3) {
    int r = blockIdx.z;
    const float* W = (r == 0 ? w1 : (r == 1 ? w2 : w3));
    const float* A = g_mean + (size_t)r * B_DIM * F_DIM;

    __shared__ float As[BK][BM];
    __shared__ float Bs[BK][BN];

    int t  = threadIdx.x;
    int tr = t >> 4;      // 0..15
    int tc = t & 15;      // 0..15
    int m0 = blockIdx.x * BM;

    float acc[4][8];
#pragma unroll
    for (int i = 0; i < 4; i++)
#pragma unroll
        for (int j = 0; j < 8; j++) acc[i][j] = 0.f;

    for (int k0 = 0; k0 < F_DIM; k0 += BK) {
        {   // A tile 64x16: one float4/thread
            int row = t >> 2, c4 = (t & 3) * 4;
            float4 v = *(const float4*)(A + (size_t)(m0 + row) * F_DIM + k0 + c4);
            As[c4 + 0][row] = v.x; As[c4 + 1][row] = v.y;
            As[c4 + 2][row] = v.z; As[c4 + 3][row] = v.w;
        }
#pragma unroll
        for (int u = 0; u < 2; u++) {  // B tile 16x128: two float4/thread
            int id = t + u * 256;
            int krow = id >> 5, n4 = (id & 31) * 4;
            *(float4*)&Bs[krow][n4] = *(const float4*)(W + (size_t)(k0 + krow) * E_DIM + n4);
        }
        __syncthreads();
#pragma unroll
        for (int k = 0; k < BK; k++) {
            float a[4], bv[8];
#pragma unroll
            for (int i = 0; i < 4; i++) a[i] = As[k][tr * 4 + i];
#pragma unroll
            for (int j = 0; j < 8; j++) bv[j] = Bs[k][tc * 8 + j];
#pragma unroll
            for (int i = 0; i < 4; i++)
#pragma unroll
                for (int j = 0; j < 8; j++) acc[i][j] += a[i] * bv[j];
        }
        __syncthreads();
    }

    float* Cb = g_cat + F_DIM + (size_t)r * E_DIM;
#pragma unroll
    for (int i = 0; i < 4; i++) {
        int m = m0 + tr * 4 + i;
        float4 v0, v1;
        v0.x = fmaxf(acc[i][0], 0.f); v0.y = fmaxf(acc[i][1], 0.f);
        v0.z = fmaxf(acc[i][2], 0.f); v0.w = fmaxf(acc[i][3], 0.f);
        v1.x = fmaxf(acc[i][4], 0.f); v1.y = fmaxf(acc[i][5], 0.f);
        v1.z = fmaxf(acc[i][6], 0.f); v1.w = fmaxf(acc[i][7], 0.f);
        *(float4*)(Cb + (size_t)m * CAT_DIM + tc * 8 + 0) = v0;
        *(float4*)(Cb + (size_t)m * CAT_DIM + tc * 8 + 4) = v1;
    }
}

// K5: combined = relu(g_cat @ weight).T -> d_out (128 x 8192)
__global__ void k_finalgemm(const float* __restrict__ W, float* __restrict__ out) {
    __shared__ float As[BK][BM];
    __shared__ float Bs[BK][BN];

    int t  = threadIdx.x;
    int tr = t >> 4;
    int tc = t & 15;
    int m0 = blockIdx.x * BM;

    float acc[4][8];
#pragma unroll
    for (int i = 0; i < 4; i++)
#pragma unroll
        for (int j = 0; j < 8; j++) acc[i][j] = 0.f;

    for (int k0 = 0; k0 < CAT_DIM; k0 += BK) {
        {
            int row = t >> 2, c4 = (t & 3) * 4;
            float4 v = *(const float4*)(g_cat + (size_t)(m0 + row) * CAT_DIM + k0 + c4);
            As[c4 + 0][row] = v.x; As[c4 + 1][row] = v.y;
            As[c4 + 2][row] = v.z; As[c4 + 3][row] = v.w;
        }
#pragma unroll
        for (int u = 0; u < 2; u++) {
            int id = t + u * 256;
            int krow = id >> 5, n4 = (id & 31) * 4;
            *(float4*)&Bs[krow][n4] = *(const float4*)(W + (size_t)(k0 + krow) * E_DIM + n4);
        }
        __syncthreads();
#pragma unroll
        for (int k = 0; k < BK; k++) {
            float a[4], bv[8];
#pragma unroll
            for (int i = 0; i < 4; i++) a[i] = As[k][tr * 4 + i];
#pragma unroll
            for (int j = 0; j < 8; j++) bv[j] = Bs[k][tc * 8 + j];
#pragma unroll
            for (int i = 0; i < 4; i++)
#pragma unroll
                for (int j = 0; j < 8; j++) acc[i][j] += a[i] * bv[j];
        }
        __syncthreads();
    }

    // transposed store: out[n * 8192 + m], relu
#pragma unroll
    for (int j = 0; j < 8; j++) {
        int n = tc * 8 + j;
        float4 v;
        v.x = fmaxf(acc[0][j], 0.f);
        v.y = fmaxf(acc[1][j], 0.f);
        v.z = fmaxf(acc[2][j], 0.f);
        v.w = fmaxf(acc[3][j], 0.f);
        *(float4*)(out + (size_t)n * B_DIM + m0 + tr * 4) = v;
    }
}

// ---------------------------------------------------------------------------
extern "C" void kernel_launch(void* const* d_in, const int* in_sizes, int n_in,
                              void* d_out, int out_size) {
    const float* features = (const float*)d_in[0];
    const int*   nodes    = (const int*)d_in[1];
    const int*   n1       = (const int*)d_in[2];
    const int*   n2       = (const int*)d_in[3];
    const int*   n3       = (const int*)d_in[4];
    const float* wc       = (const float*)d_in[5];
    const float* bc       = (const float*)d_in[6];
    const float* w1       = (const float*)d_in[7];
    const float* w2       = (const float*)d_in[8];
    const float* w3       = (const float*)d_in[9];
    const float* weight   = (const float*)d_in[10];

    float* out_combined = (float*)d_out;                       // 128 x 8192
    float* out_center   = (float*)d_out + E_DIM * B_DIM;       // 8192 x 2

    // K1: scores for all N (one warp/node, 8 warps/block)
    k_scores<<<(N_NODES + 7) / 8, 256>>>(features, wc, bc);

    // K2a: center scores gather
    k_center<<<(B_DIM + 255) / 256, 256>>>(nodes, out_center);

    // K2b: self features gather into g_cat
    k_self<<<B_DIM, 256>>>(features, nodes);

    // K3: top-K select + mean features per (b, relation)
    k_relsum<<<dim3(B_DIM, 3), 256>>>(features, nodes, n1, n2, n3);

    // K4: relation GEMMs + relu into g_cat
    k_relgemm<<<dim3(B_DIM / BM, 1, 3), 256>>>(w1, w2, w3);

    // K5: final GEMM + relu, transposed store
    k_finalgemm<<<dim3(B_DIM / BM, 1), 256>>>(weight, out_combined);
}

// round 3
// speedup vs baseline: 1.7233x; 1.7233x over previous
#include <cuda_runtime.h>
#include <cuda_bf16.h>
#include <cstdint>

#define N_NODES 100000
#define F_DIM   256
#define E_DIM   128
#define B_DIM   8192
#define D_DIM   32
#define K_SEL   16
#define CAT_DIM 640   // F + 3E

// ---------------------------------------------------------------------------
// Scratch (static device globals — no allocations allowed)
// ---------------------------------------------------------------------------
__device__ __align__(16) float          g_scores[N_NODES * 2];
__device__ __align__(16) __nv_bfloat16  g_mean_hi[3ULL * B_DIM * F_DIM];   // [r][m][k]
__device__ __align__(16) __nv_bfloat16  g_mean_lo[3ULL * B_DIM * F_DIM];
__device__ __align__(16) __nv_bfloat16  g_cat_hi[(size_t)B_DIM * CAT_DIM]; // [m][k]
__device__ __align__(16) __nv_bfloat16  g_cat_lo[(size_t)B_DIM * CAT_DIM];
__device__ __align__(16) __nv_bfloat16  g_w_hi[3 * F_DIM * E_DIM];         // [r][k][n]
__device__ __align__(16) __nv_bfloat16  g_w_lo[3 * F_DIM * E_DIM];
__device__ __align__(16) __nv_bfloat16  g_wgt_hi[CAT_DIM * E_DIM];         // [k][n]
__device__ __align__(16) __nv_bfloat16  g_wgt_lo[CAT_DIM * E_DIM];

// ---------------------------------------------------------------------------
// helpers
// ---------------------------------------------------------------------------
__device__ __forceinline__ uint32_t smem_u32(const void* p) {
    uint32_t a;
    asm("{ .reg .u64 t; cvta.to.shared.u64 t, %1; cvt.u32.u64 %0, t; }" : "=r"(a) : "l"(p));
    return a;
}
__device__ __forceinline__ void bf16split(float x, __nv_bfloat16& h, __nv_bfloat16& l) {
    h = __float2bfloat16(x);
    l = __float2bfloat16(x - __bfloat162float(h));
}
__device__ __forceinline__ uint32_t pack2(__nv_bfloat16 a, __nv_bfloat16 b) {
    __nv_bfloat162 t = __halves2bfloat162(a, b);
    return *reinterpret_cast<uint32_t*>(&t);
}
__device__ __forceinline__ void ldsm4(uint32_t* r, uint32_t addr) {
    asm volatile("ldmatrix.sync.aligned.m8n8.x4.shared.b16 {%0,%1,%2,%3}, [%4];"
                 : "=r"(r[0]), "=r"(r[1]), "=r"(r[2]), "=r"(r[3]) : "r"(addr));
}
__device__ __forceinline__ void ldsm4t(uint32_t* r, uint32_t addr) {
    asm volatile("ldmatrix.sync.aligned.m8n8.x4.trans.shared.b16 {%0,%1,%2,%3}, [%4];"
                 : "=r"(r[0]), "=r"(r[1]), "=r"(r[2]), "=r"(r[3]) : "r"(addr));
}
__device__ __forceinline__ void mma16816(float* c, const uint32_t* a, const uint32_t* b) {
    asm volatile(
        "mma.sync.aligned.m16n8k16.row.col.f32.bf16.bf16.f32 "
        "{%0,%1,%2,%3}, {%4,%5,%6,%7}, {%8,%9}, {%0,%1,%2,%3};"
        : "+f"(c[0]), "+f"(c[1]), "+f"(c[2]), "+f"(c[3])
        : "r"(a[0]), "r"(a[1]), "r"(a[2]), "r"(a[3]), "r"(b[0]), "r"(b[1]));
}

// ---------------------------------------------------------------------------
// K1: scores[n] = features[n] @ wc + bc (one warp per node)
// ---------------------------------------------------------------------------
__global__ void k_scores(const float* __restrict__ feat, const float* __restrict__ wc,
                         const float* __restrict__ bc) {
    int gwarp = (blockIdx.x * blockDim.x + threadIdx.x) >> 5;
    int lane  = threadIdx.x & 31;
    if (gwarp >= N_NODES) return;
    const float* row = feat + (size_t)gwarp * F_DIM;
    float s0 = 0.f, s1 = 0.f;
#pragma unroll
    for (int k = 0; k < 8; k++) {
        int f = k * 32 + lane;
        float v = row[f];
        s0 += v * __ldg(&wc[f * 2 + 0]);
        s1 += v * __ldg(&wc[f * 2 + 1]);
    }
#pragma unroll
    for (int o = 16; o; o >>= 1) {
        s0 += __shfl_down_sync(0xFFFFFFFFu, s0, o);
        s1 += __shfl_down_sync(0xFFFFFFFFu, s1, o);
    }
    if (lane == 0) {
        g_scores[gwarp * 2 + 0] = s0 + bc[0];
        g_scores[gwarp * 2 + 1] = s1 + bc[1];
    }
}

// ---------------------------------------------------------------------------
// K2a: center scores gather
// ---------------------------------------------------------------------------
__global__ void k_center(const int* __restrict__ nodes, float* __restrict__ out) {
    int b = blockIdx.x * blockDim.x + threadIdx.x;
    if (b < B_DIM) {
        int n = nodes[b];
        out[b * 2 + 0] = g_scores[n * 2 + 0];
        out[b * 2 + 1] = g_scores[n * 2 + 1];
    }
}

// ---------------------------------------------------------------------------
// K2b: self features -> g_cat hi/lo cols [0,256)
// ---------------------------------------------------------------------------
__global__ void k_self(const float* __restrict__ feat, const int* __restrict__ nodes) {
    int b = blockIdx.x, t = threadIdx.x;  // 64
    int node = nodes[b];
    float4 v = *(const float4*)(feat + (size_t)node * F_DIM + 4 * t);
    __nv_bfloat16 h0, h1, h2, h3, l0, l1, l2, l3;
    bf16split(v.x, h0, l0); bf16split(v.y, h1, l1);
    bf16split(v.z, h2, l2); bf16split(v.w, h3, l3);
    size_t base = (size_t)b * CAT_DIM + 4 * t;
    uint2 ph, pl;
    ph.x = pack2(h0, h1); ph.y = pack2(h2, h3);
    pl.x = pack2(l0, l1); pl.y = pack2(l2, l3);
    *(uint2*)(g_cat_hi + base) = ph;
    *(uint2*)(g_cat_lo + base) = pl;
}

// ---------------------------------------------------------------------------
// K3: stable top-K=16 by |s1-c|, mean of selected rows -> g_mean hi/lo
// ---------------------------------------------------------------------------
__global__ void k_relsum(const float* __restrict__ feat, const int* __restrict__ nodes,
                         const int* __restrict__ n1, const int* __restrict__ n2,
                         const int* __restrict__ n3) {
    int b = blockIdx.x, r = blockIdx.y, t = threadIdx.x;  // 64 threads

    __shared__ float s_d[D_DIM];
    __shared__ int   s_i[D_DIM];
    __shared__ int   s_sel[K_SEL];

    const int* nb = (r == 0 ? n1 : (r == 1 ? n2 : n3)) + (size_t)b * D_DIM;

    if (t < D_DIM) {
        int idx = nb[t];
        s_i[t] = idx;
        float c = g_scores[nodes[b] * 2 + 1];
        s_d[t] = fabsf(g_scores[idx * 2 + 1] - c);
    }
    __syncthreads();
    if (t < D_DIM) {
        float d = s_d[t];
        int rank = 0;
#pragma unroll
        for (int j = 0; j < D_DIM; j++) {
            float dj = s_d[j];
            rank += (dj < d) || (dj == d && j < t);   // stable, matches jax top_k
        }
        if (rank < K_SEL) s_sel[rank] = s_i[t];
    }
    __syncthreads();

    int sel[K_SEL];
#pragma unroll
    for (int k = 0; k < K_SEL; k++) sel[k] = s_sel[k];

    float4 acc = make_float4(0.f, 0.f, 0.f, 0.f);
#pragma unroll
    for (int k = 0; k < K_SEL; k++) {
        float4 v = *(const float4*)(feat + (size_t)sel[k] * F_DIM + 4 * t);
        acc.x += v.x; acc.y += v.y; acc.z += v.z; acc.w += v.w;
    }
    const float s = 1.0f / K_SEL;
    acc.x *= s; acc.y *= s; acc.z *= s; acc.w *= s;

    __nv_bfloat16 h0, h1, h2, h3, l0, l1, l2, l3;
    bf16split(acc.x, h0, l0); bf16split(acc.y, h1, l1);
    bf16split(acc.z, h2, l2); bf16split(acc.w, h3, l3);
    size_t base = ((size_t)r * B_DIM + b) * F_DIM + 4 * t;
    uint2 ph, pl;
    ph.x = pack2(h0, h1); ph.y = pack2(h2, h3);
    pl.x = pack2(l0, l1); pl.y = pack2(l2, l3);
    *(uint2*)(g_mean_hi + base) = ph;
    *(uint2*)(g_mean_lo + base) = pl;
}

// ---------------------------------------------------------------------------
// K_prep: bf16-split weights (already [K][N] layout — no transpose!)
// ---------------------------------------------------------------------------
__global__ void k_prep(const float* __restrict__ w1, const float* __restrict__ w2,
                       const float* __restrict__ w3, const float* __restrict__ weight) {
    int idx = blockIdx.x * blockDim.x + threadIdx.x;
    const int NW = 3 * F_DIM * E_DIM;   // 98304
    const int NG = CAT_DIM * E_DIM;     // 81920
    if (idx < NW) {
        int r = idx >> 15;              // /32768
        const float* w = (r == 0 ? w1 : (r == 1 ? w2 : w3));
        float v = w[idx & 32767];
        __nv_bfloat16 h, l; bf16split(v, h, l);
        g_w_hi[idx] = h; g_w_lo[idx] = l;
    } else if (idx < NW + NG) {
        int j = idx - NW;
        float v = weight[j];
        __nv_bfloat16 h, l; bf16split(v, h, l);
        g_wgt_hi[j] = h; g_wgt_lo[j] = l;
    }
}

// ---------------------------------------------------------------------------
// HMMA GEMM: C[128,128] tile = A[128,K] @ B[K,128], split bf16, fp32 accum.
// 8 warps = 4(m) x 2(n); warp tile 32x64; BK=64 chunks; padded SMEM.
// mode 0: relu -> bf16 split into g_cat columns [256 + r*128)
// mode 1: relu -> fp32 transposed store out[n * 8192 + m]
// ---------------------------------------------------------------------------
#define PA 144        // A row pitch bytes (64 bf16 + 16B pad)
#define PB 272        // B row pitch bytes (128 bf16 + 16B pad)
#define SA_HI 0
#define SA_LO (128 * PA)                 // 18432
#define SB_HI (2 * 128 * PA)             // 36864
#define SB_LO (2 * 128 * PA + 64 * PB)   // 54272
#define SMEM_DYN (2 * 128 * PA + 2 * 64 * PB)  // 71680

__global__ void __launch_bounds__(256)
k_gemm(const __nv_bfloat16* __restrict__ Ah, const __nv_bfloat16* __restrict__ Al,
       const __nv_bfloat16* __restrict__ Bh, const __nv_bfloat16* __restrict__ Bl,
       int K, int mode, float* __restrict__ out) {
    extern __shared__ char smem[];
    uint32_t sb = smem_u32(smem);

    int tid  = threadIdx.x;
    int lane = tid & 31;
    int warp = tid >> 5;
    int wm   = warp & 3;      // 0..3  (m)
    int wn   = warp >> 2;     // 0..1  (n)
    int m0   = blockIdx.x * 128;
    int colbase = 0;

    if (mode == 0) {
        int r = blockIdx.y;
        Ah += (size_t)r * B_DIM * K;
        Al += (size_t)r * B_DIM * K;
        Bh += (size_t)r * K * E_DIM;
        Bl += (size_t)r * K * E_DIM;
        colbase = F_DIM + r * E_DIM;
    }
    const __nv_bfloat16* At_h = Ah + (size_t)m0 * K;
    const __nv_bfloat16* At_l = Al + (size_t)m0 * K;

    // per-thread ldmatrix lane addresses
    uint32_t a_row  = wm * 32 + (lane & 7) + ((lane >> 3) & 1) * 8;
    uint32_t a_colb = (lane >> 4) * 16;
    uint32_t aoff   = a_row * PA + a_colb;
    uint32_t b_row  = (lane & 7) + ((lane >> 3) & 1) * 8;
    uint32_t b_colb = (lane >> 4) * 16 + wn * 128;
    uint32_t boff   = b_row * PB + b_colb;

    float c[2][8][4];
#pragma unroll
    for (int i = 0; i < 2; i++)
#pragma unroll
        for (int j = 0; j < 8; j++)
#pragma unroll
            for (int q = 0; q < 4; q++) c[i][j][q] = 0.f;

    const int NC = K >> 6;
    for (int ch = 0; ch < NC; ch++) {
        int kofs = ch * 64;
        __syncthreads();   // previous compute done before overwrite
        // A tiles: 128 rows x 64 bf16; 1024 x 16B units per tile
#pragma unroll
        for (int i = 0; i < 4; i++) {
            int u = tid + i * 256;
            int row = u >> 3, c16 = u & 7;
            size_t go = (size_t)row * K + kofs + c16 * 8;
            uint32_t so = row * PA + c16 * 16;
            uint4 vh = *(const uint4*)(At_h + go);
            uint4 vl = *(const uint4*)(At_l + go);
            asm volatile("st.shared.v4.b32 [%0], {%1,%2,%3,%4};" ::
                         "r"(sb + SA_HI + so), "r"(vh.x), "r"(vh.y), "r"(vh.z), "r"(vh.w) : "memory");
            asm volatile("st.shared.v4.b32 [%0], {%1,%2,%3,%4};" ::
                         "r"(sb + SA_LO + so), "r"(vl.x), "r"(vl.y), "r"(vl.z), "r"(vl.w) : "memory");
        }
        // B tiles: 64 rows x 128 bf16; 1024 x 16B units per tile
#pragma unroll
        for (int i = 0; i < 4; i++) {
            int u = tid + i * 256;
            int row = u >> 4, c16 = u & 15;
            size_t go = (size_t)(kofs + row) * E_DIM + c16 * 8;
            uint32_t so = row * PB + c16 * 16;
            uint4 vh = *(const uint4*)(Bh + go);
            uint4 vl = *(const uint4*)(Bl + go);
            asm volatile("st.shared.v4.b32 [%0], {%1,%2,%3,%4};" ::
                         "r"(sb + SB_HI + so), "r"(vh.x), "r"(vh.y), "r"(vh.z), "r"(vh.w) : "memory");
            asm volatile("st.shared.v4.b32 [%0], {%1,%2,%3,%4};" ::
                         "r"(sb + SB_LO + so), "r"(vl.x), "r"(vl.y), "r"(vl.z), "r"(vl.w) : "memory");
        }
        __syncthreads();

#pragma unroll
        for (int s = 0; s < 4; s++) {
            uint32_t ah[2][4], al_[2][4];
#pragma unroll
            for (int i = 0; i < 2; i++) {
                ldsm4(ah[i],  sb + SA_HI + aoff + i * 16 * PA + 32 * s);
                ldsm4(al_[i], sb + SA_LO + aoff + i * 16 * PA + 32 * s);
            }
            uint32_t bh[8][2], bl[8][2];
#pragma unroll
            for (int q = 0; q < 4; q++) {
                uint32_t r4[4];
                ldsm4t(r4, sb + SB_HI + boff + 16 * s * PB + q * 32);
                bh[2*q][0] = r4[0]; bh[2*q][1] = r4[1];
                bh[2*q+1][0] = r4[2]; bh[2*q+1][1] = r4[3];
                ldsm4t(r4, sb + SB_LO + boff + 16 * s * PB + q * 32);
                bl[2*q][0] = r4[0]; bl[2*q][1] = r4[1];
                bl[2*q+1][0] = r4[2]; bl[2*q+1][1] = r4[3];
            }
#pragma unroll
            for (int i = 0; i < 2; i++)
#pragma unroll
                for (int j = 0; j < 8; j++) {
                    mma16816(c[i][j], ah[i],  bh[j]);
                    mma16816(c[i][j], ah[i],  bl[j]);
                    mma16816(c[i][j], al_[i], bh[j]);
                }
        }
    }

    // epilogue: c0:(g, 2t) c1:(g, 2t+1) c2:(g+8, 2t) c3:(g+8, 2t+1)
    int g  = lane >> 2;
    int tg = lane & 3;
#pragma unroll
    for (int i = 0; i < 2; i++) {
#pragma unroll
        for (int j = 0; j < 8; j++) {
            int m = m0 + wm * 32 + i * 16 + g;
            int n = wn * 64 + j * 8 + tg * 2;
            float x0 = fmaxf(c[i][j][0], 0.f);
            float x1 = fmaxf(c[i][j][1], 0.f);
            float x2 = fmaxf(c[i][j][2], 0.f);
            float x3 = fmaxf(c[i][j][3], 0.f);
            if (mode == 0) {
                __nv_bfloat16 h0, h1, h2, h3, l0, l1, l2, l3;
                bf16split(x0, h0, l0); bf16split(x1, h1, l1);
                bf16split(x2, h2, l2); bf16split(x3, h3, l3);
                size_t p0 = (size_t)m * CAT_DIM + colbase + n;
                size_t p1 = (size_t)(m + 8) * CAT_DIM + colbase + n;
                *(uint32_t*)(g_cat_hi + p0) = pack2(h0, h1);
                *(uint32_t*)(g_cat_lo + p0) = pack2(l0, l1);
                *(uint32_t*)(g_cat_hi + p1) = pack2(h2, h3);
                *(uint32_t*)(g_cat_lo + p1) = pack2(l2, l3);
            } else {
                out[(size_t)n * B_DIM + m]           = x0;
                out[(size_t)(n + 1) * B_DIM + m]     = x1;
                out[(size_t)n * B_DIM + m + 8]       = x2;
                out[(size_t)(n + 1) * B_DIM + m + 8] = x3;
            }
        }
    }
}

// ---------------------------------------------------------------------------
extern "C" void kernel_launch(void* const* d_in, const int* in_sizes, int n_in,
                              void* d_out, int out_size) {
    const float* features = (const float*)d_in[0];
    const int*   nodes    = (const int*)d_in[1];
    const int*   n1       = (const int*)d_in[2];
    const int*   n2       = (const int*)d_in[3];
    const int*   n3       = (const int*)d_in[4];
    const float* wc       = (const float*)d_in[5];
    const float* bc       = (const float*)d_in[6];
    const float* w1       = (const float*)d_in[7];
    const float* w2       = (const float*)d_in[8];
    const float* w3       = (const float*)d_in[9];
    const float* weight   = (const float*)d_in[10];

    float* out_combined = (float*)d_out;                 // 128 x 8192
    float* out_center   = (float*)d_out + E_DIM * B_DIM; // 8192 x 2

    static bool attr_done = false;
    if (!attr_done) {
        cudaFuncSetAttribute(k_gemm, cudaFuncAttributeMaxDynamicSharedMemorySize, SMEM_DYN);
        attr_done = true;
    }

    __nv_bfloat16 *p_mean_hi, *p_mean_lo, *p_cat_hi, *p_cat_lo;
    __nv_bfloat16 *p_w_hi, *p_w_lo, *p_wgt_hi, *p_wgt_lo;
    cudaGetSymbolAddress((void**)&p_mean_hi, g_mean_hi);
    cudaGetSymbolAddress((void**)&p_mean_lo, g_mean_lo);
    cudaGetSymbolAddress((void**)&p_cat_hi,  g_cat_hi);
    cudaGetSymbolAddress((void**)&p_cat_lo,  g_cat_lo);
    cudaGetSymbolAddress((void**)&p_w_hi,    g_w_hi);
    cudaGetSymbolAddress((void**)&p_w_lo,    g_w_lo);
    cudaGetSymbolAddress((void**)&p_wgt_hi,  g_wgt_hi);
    cudaGetSymbolAddress((void**)&p_wgt_lo,  g_wgt_lo);

    // weights prep (independent of scores)
    k_prep<<<(3 * F_DIM * E_DIM + CAT_DIM * E_DIM + 255) / 256, 256>>>(w1, w2, w3, weight);

    // scores for all N
    k_scores<<<(N_NODES + 7) / 8, 256>>>(features, wc, bc);

    // center scores
    k_center<<<(B_DIM + 255) / 256, 256>>>(nodes, out_center);

    // self features -> cat
    k_self<<<B_DIM, 64>>>(features, nodes);

    // top-K + mean features
    k_relsum<<<dim3(B_DIM, 3), 64>>>(features, nodes, n1, n2, n3);

    // relation GEMMs: relu(mean @ w_r) -> cat columns (HMMA)
    k_gemm<<<dim3(B_DIM / 128, 3), 256, SMEM_DYN>>>(
        p_mean_hi, p_mean_lo, p_w_hi, p_w_lo, F_DIM, 0, out_combined);

    // final GEMM: relu(cat @ weight).T -> out (HMMA)
    k_gemm<<<dim3(B_DIM / 128, 1), 256, SMEM_DYN>>>(
        p_cat_hi, p_cat_lo, p_wgt_hi, p_wgt_lo, CAT_DIM, 1, out_combined);
}

// round 4
// speedup vs baseline: 2.1086x; 1.2236x over previous
#include <cuda_runtime.h>
#include <cuda_bf16.h>
#include <cstdint>

#define N_NODES 100000
#define F_DIM   256
#define E_DIM   128
#define B_DIM   8192
#define D_DIM   32
#define K_SEL   16
#define CAT_DIM 640   // F + 3E

// ---------------------------------------------------------------------------
// Scratch (static device globals — no allocations allowed)
// ---------------------------------------------------------------------------
__device__ __align__(16) float          g_scores[N_NODES * 2];
__device__ __align__(16) __nv_bfloat16  g_mean_hi[3ULL * B_DIM * F_DIM];   // [r][m][k]
__device__ __align__(16) __nv_bfloat16  g_mean_lo[3ULL * B_DIM * F_DIM];
__device__ __align__(16) __nv_bfloat16  g_cat_hi[(size_t)B_DIM * CAT_DIM]; // [m][k]
__device__ __align__(16) __nv_bfloat16  g_cat_lo[(size_t)B_DIM * CAT_DIM];
__device__ __align__(16) __nv_bfloat16  g_w_hi[3 * F_DIM * E_DIM];         // [r][k][n]
__device__ __align__(16) __nv_bfloat16  g_w_lo[3 * F_DIM * E_DIM];
__device__ __align__(16) __nv_bfloat16  g_wgt_hi[CAT_DIM * E_DIM];         // [k][n]
__device__ __align__(16) __nv_bfloat16  g_wgt_lo[CAT_DIM * E_DIM];

// ---------------------------------------------------------------------------
// helpers
// ---------------------------------------------------------------------------
__device__ __forceinline__ uint32_t smem_u32(const void* p) {
    uint32_t a;
    asm("{ .reg .u64 t; cvta.to.shared.u64 t, %1; cvt.u32.u64 %0, t; }" : "=r"(a) : "l"(p));
    return a;
}
__device__ __forceinline__ void bf16split(float x, __nv_bfloat16& h, __nv_bfloat16& l) {
    h = __float2bfloat16(x);
    l = __float2bfloat16(x - __bfloat162float(h));
}
__device__ __forceinline__ uint32_t pack2(__nv_bfloat16 a, __nv_bfloat16 b) {
    __nv_bfloat162 t = __halves2bfloat162(a, b);
    return *reinterpret_cast<uint32_t*>(&t);
}
__device__ __forceinline__ void ldsm4(uint32_t* r, uint32_t addr) {
    asm volatile("ldmatrix.sync.aligned.m8n8.x4.shared.b16 {%0,%1,%2,%3}, [%4];"
                 : "=r"(r[0]), "=r"(r[1]), "=r"(r[2]), "=r"(r[3]) : "r"(addr));
}
__device__ __forceinline__ void ldsm4t(uint32_t* r, uint32_t addr) {
    asm volatile("ldmatrix.sync.aligned.m8n8.x4.trans.shared.b16 {%0,%1,%2,%3}, [%4];"
                 : "=r"(r[0]), "=r"(r[1]), "=r"(r[2]), "=r"(r[3]) : "r"(addr));
}
__device__ __forceinline__ void mma16816(float* c, const uint32_t* a, const uint32_t* b) {
    asm volatile(
        "mma.sync.aligned.m16n8k16.row.col.f32.bf16.bf16.f32 "
        "{%0,%1,%2,%3}, {%4,%5,%6,%7}, {%8,%9}, {%0,%1,%2,%3};"
        : "+f"(c[0]), "+f"(c[1]), "+f"(c[2]), "+f"(c[3])
        : "r"(a[0]), "r"(a[1]), "r"(a[2]), "r"(a[3]), "r"(b[0]), "r"(b[1]));
}
__device__ __forceinline__ void cp16(uint32_t s, const void* g) {
    asm volatile("cp.async.cg.shared.global [%0], [%1], 16;" :: "r"(s), "l"(g));
}
#define CP_COMMIT() asm volatile("cp.async.commit_group;" ::: "memory")
#define CP_WAIT(n)  asm volatile("cp.async.wait_group %0;" :: "n"(n) : "memory")

// ---------------------------------------------------------------------------
// K1: scores[n] = features[n] @ wc + bc (one warp per node)
// ---------------------------------------------------------------------------
__global__ void k_scores(const float* __restrict__ feat, const float* __restrict__ wc,
                         const float* __restrict__ bc) {
    int gwarp = (blockIdx.x * blockDim.x + threadIdx.x) >> 5;
    int lane  = threadIdx.x & 31;
    if (gwarp >= N_NODES) return;
    const float* row = feat + (size_t)gwarp * F_DIM;
    float s0 = 0.f, s1 = 0.f;
#pragma unroll
    for (int k = 0; k < 8; k++) {
        int f = k * 32 + lane;
        float v = row[f];
        s0 += v * __ldg(&wc[f * 2 + 0]);
        s1 += v * __ldg(&wc[f * 2 + 1]);
    }
#pragma unroll
    for (int o = 16; o; o >>= 1) {
        s0 += __shfl_down_sync(0xFFFFFFFFu, s0, o);
        s1 += __shfl_down_sync(0xFFFFFFFFu, s1, o);
    }
    if (lane == 0) {
        g_scores[gwarp * 2 + 0] = s0 + bc[0];
        g_scores[gwarp * 2 + 1] = s1 + bc[1];
    }
}

// ---------------------------------------------------------------------------
// K2: self features -> g_cat cols [0,256) + center scores -> d_out tail.
// 256 threads, 4 batch rows per block.
// ---------------------------------------------------------------------------
__global__ void k_self(const float* __restrict__ feat, const int* __restrict__ nodes,
                       float* __restrict__ out_center) {
    int b = blockIdx.x * 4 + (threadIdx.x >> 6);
    int t = threadIdx.x & 63;
    int node = nodes[b];
    float4 v = *(const float4*)(feat + (size_t)node * F_DIM + 4 * t);
    __nv_bfloat16 h0, h1, h2, h3, l0, l1, l2, l3;
    bf16split(v.x, h0, l0); bf16split(v.y, h1, l1);
    bf16split(v.z, h2, l2); bf16split(v.w, h3, l3);
    size_t base = (size_t)b * CAT_DIM + 4 * t;
    uint2 ph, pl;
    ph.x = pack2(h0, h1); ph.y = pack2(h2, h3);
    pl.x = pack2(l0, l1); pl.y = pack2(l2, l3);
    *(uint2*)(g_cat_hi + base) = ph;
    *(uint2*)(g_cat_lo + base) = pl;
    if (t < 2) out_center[b * 2 + t] = g_scores[node * 2 + t];
}

// ---------------------------------------------------------------------------
// K3: stable top-K=16 by |s1-c|, mean of selected rows -> g_mean hi/lo
// ---------------------------------------------------------------------------
__global__ void k_relsum(const float* __restrict__ feat, const int* __restrict__ nodes,
                         const int* __restrict__ n1, const int* __restrict__ n2,
                         const int* __restrict__ n3) {
    int b = blockIdx.x, r = blockIdx.y, t = threadIdx.x;  // 64 threads

    __shared__ float s_d[D_DIM];
    __shared__ int   s_i[D_DIM];
    __shared__ int   s_sel[K_SEL];

    const int* nb = (r == 0 ? n1 : (r == 1 ? n2 : n3)) + (size_t)b * D_DIM;

    if (t < D_DIM) {
        int idx = nb[t];
        s_i[t] = idx;
        float c = g_scores[nodes[b] * 2 + 1];
        s_d[t] = fabsf(g_scores[idx * 2 + 1] - c);
    }
    __syncthreads();
    if (t < D_DIM) {
        float d = s_d[t];
        int rank = 0;
#pragma unroll
        for (int j = 0; j < D_DIM; j++) {
            float dj = s_d[j];
            rank += (dj < d) || (dj == d && j < t);   // stable, matches jax top_k
        }
        if (rank < K_SEL) s_sel[rank] = s_i[t];
    }
    __syncthreads();

    int sel[K_SEL];
#pragma unroll
    for (int k = 0; k < K_SEL; k++) sel[k] = s_sel[k];

    float4 acc = make_float4(0.f, 0.f, 0.f, 0.f);
#pragma unroll
    for (int k = 0; k < K_SEL; k++) {
        float4 v = *(const float4*)(feat + (size_t)sel[k] * F_DIM + 4 * t);
        acc.x += v.x; acc.y += v.y; acc.z += v.z; acc.w += v.w;
    }
    const float s = 1.0f / K_SEL;
    acc.x *= s; acc.y *= s; acc.z *= s; acc.w *= s;

    __nv_bfloat16 h0, h1, h2, h3, l0, l1, l2, l3;
    bf16split(acc.x, h0, l0); bf16split(acc.y, h1, l1);
    bf16split(acc.z, h2, l2); bf16split(acc.w, h3, l3);
    size_t base = ((size_t)r * B_DIM + b) * F_DIM + 4 * t;
    uint2 ph, pl;
    ph.x = pack2(h0, h1); ph.y = pack2(h2, h3);
    pl.x = pack2(l0, l1); pl.y = pack2(l2, l3);
    *(uint2*)(g_mean_hi + base) = ph;
    *(uint2*)(g_mean_lo + base) = pl;
}

// ---------------------------------------------------------------------------
// K_prep: bf16-split weights (already [K][N] layout — no transpose)
// ---------------------------------------------------------------------------
__global__ void k_prep(const float* __restrict__ w1, const float* __restrict__ w2,
                       const float* __restrict__ w3, const float* __restrict__ weight) {
    int idx = blockIdx.x * blockDim.x + threadIdx.x;
    const int NW = 3 * F_DIM * E_DIM;   // 98304
    const int NG = CAT_DIM * E_DIM;     // 81920
    if (idx < NW) {
        int r = idx >> 15;
        const float* w = (r == 0 ? w1 : (r == 1 ? w2 : w3));
        float v = w[idx & 32767];
        __nv_bfloat16 h, l; bf16split(v, h, l);
        g_w_hi[idx] = h; g_w_lo[idx] = l;
    } else if (idx < NW + NG) {
        int j = idx - NW;
        float v = weight[j];
        __nv_bfloat16 h, l; bf16split(v, h, l);
        g_wgt_hi[j] = h; g_wgt_lo[j] = l;
    }
}

// ---------------------------------------------------------------------------
// HMMA GEMM, cp.async 2-stage pipelined. C[BM,128] = A[BM,K] @ B[K,128].
// Split bf16: Ah*Bh + Ah*Bl + Al*Bh, fp32 accum.
// BM=128: 8 warps = 4m x 2n (warp 32x64). BM=64: 2m x 4n (warp 32x32).
// mode 0: relu -> bf16 split into g_cat cols [colbase..); mode 1: relu -> out.T
// ---------------------------------------------------------------------------
#define PA 144        // A row pitch bytes (64 bf16 + 16B pad)
#define PB 272        // B row pitch bytes (128 bf16 + 16B pad)

template<int BM>
__device__ __forceinline__ void stage_load(
    uint32_t base, const __nv_bfloat16* __restrict__ At_h,
    const __nv_bfloat16* __restrict__ At_l, const __nv_bfloat16* __restrict__ Bh,
    const __nv_bfloat16* __restrict__ Bl, int K, int kofs, int tid) {
    constexpr int SA  = BM * PA;
    constexpr int SBT = 64 * PB;
#pragma unroll
    for (int u = tid; u < BM * 8; u += 256) {
        int row = u >> 3, c16 = u & 7;
        size_t go = (size_t)row * K + kofs + c16 * 8;
        uint32_t so = row * PA + c16 * 16;
        cp16(base + so,      At_h + go);
        cp16(base + SA + so, At_l + go);
    }
#pragma unroll
    for (int u = tid; u < 64 * 16; u += 256) {
        int row = u >> 4, c16 = u & 15;
        size_t go = (size_t)(kofs + row) * E_DIM + c16 * 8;
        uint32_t so = row * PB + c16 * 16;
        cp16(base + 2 * SA + so,       Bh + go);
        cp16(base + 2 * SA + SBT + so, Bl + go);
    }
}

template<int BM>
__global__ void __launch_bounds__(256)
k_gemm(const __nv_bfloat16* __restrict__ Ah, const __nv_bfloat16* __restrict__ Al,
       const __nv_bfloat16* __restrict__ Bh, const __nv_bfloat16* __restrict__ Bl,
       int K, int mode, float* __restrict__ out) {
    constexpr int WMN = (BM == 128) ? 4 : 2;   // warps along m
    constexpr int JN  = (BM == 128) ? 8 : 4;   // 8-col n fragments per warp
    constexpr int SA  = BM * PA;
    constexpr int SBT = 64 * PB;
    constexpr int STAGE = 2 * SA + 2 * SBT;

    extern __shared__ char smem[];
    uint32_t sb = smem_u32(smem);

    int tid  = threadIdx.x;
    int lane = tid & 31;
    int warp = tid >> 5;
    int wm   = warp % WMN;
    int wn   = warp / WMN;
    int m0   = blockIdx.x * BM;
    int colbase = 0;

    if (mode == 0) {
        int r = blockIdx.y;
        Ah += (size_t)r * B_DIM * K;
        Al += (size_t)r * B_DIM * K;
        Bh += (size_t)r * K * E_DIM;
        Bl += (size_t)r * K * E_DIM;
        colbase = F_DIM + r * E_DIM;
    }
    const __nv_bfloat16* At_h = Ah + (size_t)m0 * K;
    const __nv_bfloat16* At_l = Al + (size_t)m0 * K;

    uint32_t aoff = (wm * 32 + (lane & 7) + ((lane >> 3) & 1) * 8) * PA + (lane >> 4) * 16;
    uint32_t boff = ((lane & 7) + ((lane >> 3) & 1) * 8) * PB + (lane >> 4) * 16
                  + wn * (JN * 8) * 2;

    float c[2][JN][4];
#pragma unroll
    for (int i = 0; i < 2; i++)
#pragma unroll
        for (int j = 0; j < JN; j++)
#pragma unroll
            for (int q = 0; q < 4; q++) c[i][j][q] = 0.f;

    const int NC = K >> 6;

    stage_load<BM>(sb, At_h, At_l, Bh, Bl, K, 0, tid);
    CP_COMMIT();

    for (int ch = 0; ch < NC; ch++) {
        if (ch + 1 < NC) {
            stage_load<BM>(sb + ((ch + 1) & 1) * STAGE, At_h, At_l, Bh, Bl, K,
                           (ch + 1) * 64, tid);
            CP_COMMIT();
            CP_WAIT(1);
        } else {
            CP_WAIT(0);
        }
        __syncthreads();

        uint32_t base = sb + (ch & 1) * STAGE;
#pragma unroll
        for (int s = 0; s < 4; s++) {
            uint32_t ah[2][4], al_[2][4];
#pragma unroll
            for (int i = 0; i < 2; i++) {
                ldsm4(ah[i],  base + aoff + i * 16 * PA + 32 * s);
                ldsm4(al_[i], base + SA + aoff + i * 16 * PA + 32 * s);
            }
            uint32_t bh[JN][2], bl[JN][2];
#pragma unroll
            for (int q = 0; q < JN / 2; q++) {
                uint32_t r4[4];
                ldsm4t(r4, base + 2 * SA + boff + 16 * s * PB + q * 32);
                bh[2*q][0] = r4[0]; bh[2*q][1] = r4[1];
                bh[2*q+1][0] = r4[2]; bh[2*q+1][1] = r4[3];
                ldsm4t(r4, base + 2 * SA + SBT + boff + 16 * s * PB + q * 32);
                bl[2*q][0] = r4[0]; bl[2*q][1] = r4[1];
                bl[2*q+1][0] = r4[2]; bl[2*q+1][1] = r4[3];
            }
#pragma unroll
            for (int i = 0; i < 2; i++)
#pragma unroll
                for (int j = 0; j < JN; j++) {
                    mma16816(c[i][j], ah[i],  bh[j]);
                    mma16816(c[i][j], ah[i],  bl[j]);
                    mma16816(c[i][j], al_[i], bh[j]);
                }
        }
        __syncthreads();   // compute done before this stage is overwritten
    }

    int g  = lane >> 2;
    int tg = lane & 3;
#pragma unroll
    for (int i = 0; i < 2; i++) {
#pragma unroll
        for (int j = 0; j < JN; j++) {
            int m = m0 + wm * 32 + i * 16 + g;
            int n = wn * (JN * 8) + j * 8 + tg * 2;
            float x0 = fmaxf(c[i][j][0], 0.f);
            float x1 = fmaxf(c[i][j][1], 0.f);
            float x2 = fmaxf(c[i][j][2], 0.f);
            float x3 = fmaxf(c[i][j][3], 0.f);
            if (mode == 0) {
                __nv_bfloat16 h0, h1, h2, h3, l0, l1, l2, l3;
                bf16split(x0, h0, l0); bf16split(x1, h1, l1);
                bf16split(x2, h2, l2); bf16split(x3, h3, l3);
                size_t p0 = (size_t)m * CAT_DIM + colbase + n;
                size_t p1 = (size_t)(m + 8) * CAT_DIM + colbase + n;
                *(uint32_t*)(g_cat_hi + p0) = pack2(h0, h1);
                *(uint32_t*)(g_cat_lo + p0) = pack2(l0, l1);
                *(uint32_t*)(g_cat_hi + p1) = pack2(h2, h3);
                *(uint32_t*)(g_cat_lo + p1) = pack2(l2, l3);
            } else {
                out[(size_t)n * B_DIM + m]           = x0;
                out[(size_t)(n + 1) * B_DIM + m]     = x1;
                out[(size_t)n * B_DIM + m + 8]       = x2;
                out[(size_t)(n + 1) * B_DIM + m + 8] = x3;
            }
        }
    }
}

#define SMEM_G128 (2 * (2 * 128 * PA + 2 * 64 * PB))   // 143360
#define SMEM_G64  (2 * (2 * 64 * PA + 2 * 64 * PB))    // 106496

// ---------------------------------------------------------------------------
extern "C" void kernel_launch(void* const* d_in, const int* in_sizes, int n_in,
                              void* d_out, int out_size) {
    const float* features = (const float*)d_in[0];
    const int*   nodes    = (const int*)d_in[1];
    const int*   n1       = (const int*)d_in[2];
    const int*   n2       = (const int*)d_in[3];
    const int*   n3       = (const int*)d_in[4];
    const float* wc       = (const float*)d_in[5];
    const float* bc       = (const float*)d_in[6];
    const float* w1       = (const float*)d_in[7];
    const float* w2       = (const float*)d_in[8];
    const float* w3       = (const float*)d_in[9];
    const float* weight   = (const float*)d_in[10];

    float* out_combined = (float*)d_out;                 // 128 x 8192
    float* out_center   = (float*)d_out + E_DIM * B_DIM; // 8192 x 2

    static bool attr_done = false;
    if (!attr_done) {
        cudaFuncSetAttribute(k_gemm<128>, cudaFuncAttributeMaxDynamicSharedMemorySize, SMEM_G128);
        cudaFuncSetAttribute(k_gemm<64>,  cudaFuncAttributeMaxDynamicSharedMemorySize, SMEM_G64);
        attr_done = true;
    }

    __nv_bfloat16 *p_mean_hi, *p_mean_lo, *p_cat_hi, *p_cat_lo;
    __nv_bfloat16 *p_w_hi, *p_w_lo, *p_wgt_hi, *p_wgt_lo;
    cudaGetSymbolAddress((void**)&p_mean_hi, g_mean_hi);
    cudaGetSymbolAddress((void**)&p_mean_lo, g_mean_lo);
    cudaGetSymbolAddress((void**)&p_cat_hi,  g_cat_hi);
    cudaGetSymbolAddress((void**)&p_cat_lo,  g_cat_lo);
    cudaGetSymbolAddress((void**)&p_w_hi,    g_w_hi);
    cudaGetSymbolAddress((void**)&p_w_lo,    g_w_lo);
    cudaGetSymbolAddress((void**)&p_wgt_hi,  g_wgt_hi);
    cudaGetSymbolAddress((void**)&p_wgt_lo,  g_wgt_lo);

    // weights prep (independent of scores)
    k_prep<<<(3 * F_DIM * E_DIM + CAT_DIM * E_DIM + 255) / 256, 256>>>(w1, w2, w3, weight);

    // scores for all N
    k_scores<<<(N_NODES + 7) / 8, 256>>>(features, wc, bc);

    // self features -> cat + center scores (after scores)
    k_self<<<B_DIM / 4, 256>>>(features, nodes, out_center);

    // top-K + mean features
    k_relsum<<<dim3(B_DIM, 3), 64>>>(features, nodes, n1, n2, n3);

    // relation GEMMs: relu(mean @ w_r) -> cat columns (HMMA, pipelined)
    k_gemm<128><<<dim3(B_DIM / 128, 3), 256, SMEM_G128>>>(
        p_mean_hi, p_mean_lo, p_w_hi, p_w_lo, F_DIM, 0, out_combined);

    // final GEMM: relu(cat @ weight).T -> out (HMMA, BM=64 for full-chip grid)
    k_gemm<64><<<dim3(B_DIM / 64, 1), 256, SMEM_G64>>>(
        p_cat_hi, p_cat_lo, p_wgt_hi, p_wgt_lo, CAT_DIM, 1, out_combined);
}